// round 3
// baseline (speedup 1.0000x reference)
#include <cuda_runtime.h>
#include <math.h>

// Problem constants (MoDRouter_48387101556956: fixed shapes)
#define BB   4
#define NN   4096
#define DD   1024
#define DFFN 4096
#define KK   2048
#define MM   (BB * KK)   // 8192 selected tokens total

// ---------------------------------------------------------------------------
// Device scratch (no allocations allowed in kernel_launch)
// ---------------------------------------------------------------------------
__device__ float g_scores[BB * NN];
__device__ int   g_sel[BB * KK];                    // selected token index (0..NN-1) per batch
__device__ float g_h[(size_t)MM * DFFN];            // GELU(x_sel @ w1 + b1), 128 MiB

// ---------------------------------------------------------------------------
// 1) Gate scores: scores[b,n] = dot(x[b,n,:], gate_w)  — one warp per row
// ---------------------------------------------------------------------------
__global__ void scores_kernel(const float* __restrict__ x,
                              const float* __restrict__ gw) {
    int gwarp = (blockIdx.x * blockDim.x + threadIdx.x) >> 5;
    int lane  = threadIdx.x & 31;
    if (gwarp >= BB * NN) return;
    const float4* xr = reinterpret_cast<const float4*>(x + (size_t)gwarp * DD);
    const float4* g4 = reinterpret_cast<const float4*>(gw);
    float s = 0.0f;
#pragma unroll
    for (int i = 0; i < DD / 4 / 32; ++i) {   // 8 float4 per lane
        float4 a = xr[lane + i * 32];
        float4 b = g4[lane + i * 32];
        s += a.x * b.x + a.y * b.y + a.z * b.z + a.w * b.w;
    }
#pragma unroll
    for (int o = 16; o; o >>= 1) s += __shfl_xor_sync(0xFFFFFFFFu, s, o);
    if (lane == 0) g_scores[gwarp] = s;
}

// ---------------------------------------------------------------------------
// 2) Per-batch top-K: bitonic sort 4096 (score,idx) pairs in smem (ascending),
//    take the last K indices. Order within the set is irrelevant downstream.
// ---------------------------------------------------------------------------
__global__ void topk_kernel() {
    __shared__ float key[NN];
    __shared__ int   val[NN];
    int b = blockIdx.x;
    for (int i = threadIdx.x; i < NN; i += blockDim.x) {
        key[i] = g_scores[b * NN + i];
        val[i] = i;
    }
    __syncthreads();
    for (int k = 2; k <= NN; k <<= 1) {
        for (int j = k >> 1; j > 0; j >>= 1) {
            for (int i = threadIdx.x; i < NN; i += blockDim.x) {
                int ixj = i ^ j;
                if (ixj > i) {
                    bool up = ((i & k) == 0);
                    float ki = key[i], kj = key[ixj];
                    bool do_swap = up ? (ki > kj) : (ki < kj);
                    if (do_swap) {
                        key[i] = kj; key[ixj] = ki;
                        int t = val[i]; val[i] = val[ixj]; val[ixj] = t;
                    }
                }
            }
            __syncthreads();
        }
    }
    for (int i = threadIdx.x; i < KK; i += blockDim.x)
        g_sel[b * KK + i] = val[NN - 1 - i];
}

// ---------------------------------------------------------------------------
// 3) out = x (full copy); selected rows get overwritten by ffn2 scatter
// ---------------------------------------------------------------------------
__global__ void copy_kernel(const float* __restrict__ x, float* __restrict__ out) {
    size_t n4 = (size_t)BB * NN * DD / 4;
    const float4* src = reinterpret_cast<const float4*>(x);
    float4*       dst = reinterpret_cast<float4*>(out);
    for (size_t i = blockIdx.x * (size_t)blockDim.x + threadIdx.x; i < n4;
         i += (size_t)gridDim.x * blockDim.x)
        dst[i] = src[i];
}

// ---------------------------------------------------------------------------
// SGEMM tiling: 128x128 block tile, K=8 step, 256 threads, 8x8 micro-tile
// ---------------------------------------------------------------------------
#define BM 128
#define BN 128
#define BK 8
#define TM 8
#define TN 8

__device__ __forceinline__ float gelu_tanh(float u) {
    float t = tanhf(0.7978845608028654f * (u + 0.044715f * u * u * u));
    return 0.5f * u * (1.0f + t);
}

// 4) GEMM1 (gathered A) + bias + GELU:  g_h = gelu(x[sel] @ w1 + b1)
__global__ __launch_bounds__(256, 2)
void ffn1_kernel(const float* __restrict__ x,
                 const float* __restrict__ w1,
                 const float* __restrict__ b1) {
    __shared__ float    As[BK][BM];
    __shared__ float    Bs[BK][BN];
    __shared__ unsigned rowtok[BM];   // (b*NN + tok) for each local row

    int mt = blockIdx.y, nt = blockIdx.x;
    int tid = threadIdx.x;
    if (tid < BM) {
        int m = mt * BM + tid;
        int b = m / KK, j = m % KK;
        rowtok[tid] = (unsigned)(b * NN + g_sel[b * KK + j]);
    }
    __syncthreads();

    int tx = tid % 16, ty = tid / 16;
    int arow = tid >> 1, acol = (tid & 1) * 4;
    int brow = tid >> 5, bcol = (tid & 31) * 4;

    float acc[TM][TN] = {};
    const float* Bp = w1 + nt * BN;
    size_t abase = (size_t)rowtok[arow] * DD;

    for (int k0 = 0; k0 < DD; k0 += BK) {
        float4 av = *reinterpret_cast<const float4*>(x + abase + k0 + acol);
        As[acol + 0][arow] = av.x;
        As[acol + 1][arow] = av.y;
        As[acol + 2][arow] = av.z;
        As[acol + 3][arow] = av.w;
        *reinterpret_cast<float4*>(&Bs[brow][bcol]) =
            *reinterpret_cast<const float4*>(Bp + (size_t)(k0 + brow) * DFFN + bcol);
        __syncthreads();
#pragma unroll
        for (int kk = 0; kk < BK; ++kk) {
            float ra[TM], rb[TN];
            *reinterpret_cast<float4*>(ra)     = *reinterpret_cast<const float4*>(&As[kk][ty * TM]);
            *reinterpret_cast<float4*>(ra + 4) = *reinterpret_cast<const float4*>(&As[kk][ty * TM + 4]);
            *reinterpret_cast<float4*>(rb)     = *reinterpret_cast<const float4*>(&Bs[kk][tx * TN]);
            *reinterpret_cast<float4*>(rb + 4) = *reinterpret_cast<const float4*>(&Bs[kk][tx * TN + 4]);
#pragma unroll
            for (int i = 0; i < TM; ++i)
#pragma unroll
                for (int j = 0; j < TN; ++j)
                    acc[i][j] += ra[i] * rb[j];
        }
        __syncthreads();
    }

    int n0 = nt * BN + tx * TN;
    float bias[TN];
    *reinterpret_cast<float4*>(bias)     = *reinterpret_cast<const float4*>(b1 + n0);
    *reinterpret_cast<float4*>(bias + 4) = *reinterpret_cast<const float4*>(b1 + n0 + 4);
#pragma unroll
    for (int i = 0; i < TM; ++i) {
        int m = mt * BM + ty * TM + i;
        float* hp = g_h + (size_t)m * DFFN + n0;
        float v[TN];
#pragma unroll
        for (int j = 0; j < TN; ++j)
            v[j] = gelu_tanh(acc[i][j] + bias[j]);
        *reinterpret_cast<float4*>(hp)     = *reinterpret_cast<float4*>(v);
        *reinterpret_cast<float4*>(hp + 4) = *reinterpret_cast<float4*>(v + 4);
    }
}

// 5) GEMM2 + bias + residual + scatter:  out[b, sel] = x[b, sel] + g_h @ w2 + b2
__global__ __launch_bounds__(256, 2)
void ffn2_kernel(const float* __restrict__ x,
                 const float* __restrict__ w2,
                 const float* __restrict__ b2,
                 float* __restrict__ out) {
    __shared__ float    As[BK][BM];
    __shared__ float    Bs[BK][BN];
    __shared__ unsigned rowtok[BM];

    int mt = blockIdx.y, nt = blockIdx.x;
    int tid = threadIdx.x;
    if (tid < BM) {
        int m = mt * BM + tid;
        int b = m / KK, j = m % KK;
        rowtok[tid] = (unsigned)(b * NN + g_sel[b * KK + j]);
    }
    __syncthreads();

    int tx = tid % 16, ty = tid / 16;
    int arow = tid >> 1, acol = (tid & 1) * 4;
    int brow = tid >> 5, bcol = (tid & 31) * 4;

    float acc[TM][TN] = {};
    const float* Ap = g_h + (size_t)(mt * BM + arow) * DFFN;
    const float* Bp = w2 + nt * BN;

    for (int k0 = 0; k0 < DFFN; k0 += BK) {
        float4 av = *reinterpret_cast<const float4*>(Ap + k0 + acol);
        As[acol + 0][arow] = av.x;
        As[acol + 1][arow] = av.y;
        As[acol + 2][arow] = av.z;
        As[acol + 3][arow] = av.w;
        *reinterpret_cast<float4*>(&Bs[brow][bcol]) =
            *reinterpret_cast<const float4*>(Bp + (size_t)(k0 + brow) * DD + bcol);
        __syncthreads();
#pragma unroll
        for (int kk = 0; kk < BK; ++kk) {
            float ra[TM], rb[TN];
            *reinterpret_cast<float4*>(ra)     = *reinterpret_cast<const float4*>(&As[kk][ty * TM]);
            *reinterpret_cast<float4*>(ra + 4) = *reinterpret_cast<const float4*>(&As[kk][ty * TM + 4]);
            *reinterpret_cast<float4*>(rb)     = *reinterpret_cast<const float4*>(&Bs[kk][tx * TN]);
            *reinterpret_cast<float4*>(rb + 4) = *reinterpret_cast<const float4*>(&Bs[kk][tx * TN + 4]);
#pragma unroll
            for (int i = 0; i < TM; ++i)
#pragma unroll
                for (int j = 0; j < TN; ++j)
                    acc[i][j] += ra[i] * rb[j];
        }
        __syncthreads();
    }

    int n0 = nt * BN + tx * TN;
    float bias[TN];
    *reinterpret_cast<float4*>(bias)     = *reinterpret_cast<const float4*>(b2 + n0);
    *reinterpret_cast<float4*>(bias + 4) = *reinterpret_cast<const float4*>(b2 + n0 + 4);
#pragma unroll
    for (int i = 0; i < TM; ++i) {
        size_t base = (size_t)rowtok[ty * TM + i] * DD + n0;
        float4 x0 = *reinterpret_cast<const float4*>(x + base);
        float4 x1 = *reinterpret_cast<const float4*>(x + base + 4);
        float v[TN];
        v[0] = x0.x + acc[i][0] + bias[0];
        v[1] = x0.y + acc[i][1] + bias[1];
        v[2] = x0.z + acc[i][2] + bias[2];
        v[3] = x0.w + acc[i][3] + bias[3];
        v[4] = x1.x + acc[i][4] + bias[4];
        v[5] = x1.y + acc[i][5] + bias[5];
        v[6] = x1.z + acc[i][6] + bias[6];
        v[7] = x1.w + acc[i][7] + bias[7];
        *reinterpret_cast<float4*>(out + base)     = *reinterpret_cast<float4*>(v);
        *reinterpret_cast<float4*>(out + base + 4) = *reinterpret_cast<float4*>(v + 4);
    }
}

// ---------------------------------------------------------------------------
// Launch: inputs are x, gate_w, w1, b1, w2, b2, k (metadata order)
// ---------------------------------------------------------------------------
extern "C" void kernel_launch(void* const* d_in, const int* in_sizes, int n_in,
                              void* d_out, int out_size) {
    const float* x  = (const float*)d_in[0];
    const float* gw = (const float*)d_in[1];
    const float* w1 = (const float*)d_in[2];
    const float* b1 = (const float*)d_in[3];
    const float* w2 = (const float*)d_in[4];
    const float* b2 = (const float*)d_in[5];
    float* out = (float*)d_out;

    // 1) gate scores: 16384 rows, one warp each -> 2048 blocks of 256
    scores_kernel<<<(BB * NN) / 8, 256>>>(x, gw);
    // 2) per-batch top-K
    topk_kernel<<<BB, 1024>>>();
    // 3) out = x
    copy_kernel<<<4096, 256>>>(x, out);
    // 4) h = gelu(x_sel @ w1 + b1)
    ffn1_kernel<<<dim3(DFFN / BN, MM / BM), 256>>>(x, w1, b1);
    // 5) out[sel] = x_sel + h @ w2 + b2
    ffn2_kernel<<<dim3(DD / BN, MM / BM), 256>>>(x, w2, b2, out);
}

// round 5
// speedup vs baseline: 3.3800x; 3.3800x over previous
#include <cuda_runtime.h>
#include <cstdint>
#include <math.h>

// Problem constants (MoDRouter_48387101556956: fixed shapes)
#define BB   4
#define NN   4096
#define DD   1024
#define DFFN 4096
#define KK   2048
#define MM   (BB * KK)   // 8192 selected tokens total

// ---------------------------------------------------------------------------
// Device scratch
// ---------------------------------------------------------------------------
__device__ float g_scores[BB * NN];
__device__ int   g_sel[MM];                       // selected token idx per (b,j)
__device__ float g_a[(size_t)MM * DD];            // gathered + tf32-rounded A (32 MB)
__device__ float g_w1t[(size_t)DFFN * DD];        // w1^T (n-major, K contig), tf32-rounded
__device__ float g_w2t[(size_t)DD * DFFN];        // w2^T (n-major, K contig), tf32-rounded
__device__ float g_h[(size_t)MM * DFFN];          // gelu(x@w1+b1), tf32-rounded (128 MB)

// ---------------------------------------------------------------------------
// Helpers
// ---------------------------------------------------------------------------
__device__ __forceinline__ uint32_t smem_u32(const void* p) {
    uint32_t a;
    asm("{ .reg .u64 t; cvta.to.shared.u64 t, %1; cvt.u32.u64 %0, t; }" : "=r"(a) : "l"(p));
    return a;
}
__device__ __forceinline__ float rna_tf32(float f) {
    uint32_t u;
    asm("cvt.rna.tf32.f32 %0, %1;" : "=r"(u) : "f"(f));
    return __uint_as_float(u);
}
__device__ __forceinline__ float gelu_tanh(float u) {
    float t = tanhf(0.7978845608028654f * (u + 0.044715f * u * u * u));
    return 0.5f * u * (1.0f + t);
}

#define CP_ASYNC16(dst, src) \
    asm volatile("cp.async.cg.shared.global [%0], [%1], 16;" :: "r"(dst), "l"(src) : "memory")
#define CP_COMMIT() asm volatile("cp.async.commit_group;" ::: "memory")
#define CP_WAIT1()  asm volatile("cp.async.wait_group 1;" ::: "memory")
#define CP_WAIT0()  asm volatile("cp.async.wait_group 0;" ::: "memory")

// m16n8k8 row.col tf32 MMA, fp32 accumulate (base-ISA, works on sm_103)
#define MMA_TF32(c, a, b0, b1)                                                        \
    asm volatile("mma.sync.aligned.m16n8k8.row.col.f32.tf32.tf32.f32 "                \
                 "{%0,%1,%2,%3}, {%4,%5,%6,%7}, {%8,%9}, {%0,%1,%2,%3};"              \
                 : "+f"((c)[0]), "+f"((c)[1]), "+f"((c)[2]), "+f"((c)[3])             \
                 : "r"((a)[0]), "r"((a)[1]), "r"((a)[2]), "r"((a)[3]), "r"(b0), "r"(b1))

// ---------------------------------------------------------------------------
// 1) Gate scores — one warp per row
// ---------------------------------------------------------------------------
__global__ void scores_kernel(const float* __restrict__ x, const float* __restrict__ gw) {
    int gwarp = (blockIdx.x * blockDim.x + threadIdx.x) >> 5;
    int lane  = threadIdx.x & 31;
    if (gwarp >= BB * NN) return;
    const float4* xr = reinterpret_cast<const float4*>(x + (size_t)gwarp * DD);
    const float4* g4 = reinterpret_cast<const float4*>(gw);
    float s = 0.0f;
#pragma unroll
    for (int i = 0; i < DD / 4 / 32; ++i) {
        float4 a = xr[lane + i * 32];
        float4 b = g4[lane + i * 32];
        s += a.x * b.x + a.y * b.y + a.z * b.z + a.w * b.w;
    }
#pragma unroll
    for (int o = 16; o; o >>= 1) s += __shfl_xor_sync(0xFFFFFFFFu, s, o);
    if (lane == 0) g_scores[gwarp] = s;
}

// ---------------------------------------------------------------------------
// 2) Per-batch top-K via bitonic sort (verified in R1)
// ---------------------------------------------------------------------------
__global__ void topk_kernel() {
    __shared__ float key[NN];
    __shared__ int   val[NN];
    int b = blockIdx.x;
    for (int i = threadIdx.x; i < NN; i += blockDim.x) { key[i] = g_scores[b * NN + i]; val[i] = i; }
    __syncthreads();
    for (int k = 2; k <= NN; k <<= 1)
        for (int j = k >> 1; j > 0; j >>= 1) {
            for (int i = threadIdx.x; i < NN; i += blockDim.x) {
                int ixj = i ^ j;
                if (ixj > i) {
                    bool up = ((i & k) == 0);
                    float ki = key[i], kj = key[ixj];
                    if (up ? (ki > kj) : (ki < kj)) {
                        key[i] = kj; key[ixj] = ki;
                        int t = val[i]; val[i] = val[ixj]; val[ixj] = t;
                    }
                }
            }
            __syncthreads();
        }
    for (int i = threadIdx.x; i < KK; i += blockDim.x)
        g_sel[b * KK + i] = val[NN - 1 - i];
}

// ---------------------------------------------------------------------------
// 3) out = x
// ---------------------------------------------------------------------------
__global__ void copy_kernel(const float* __restrict__ x, float* __restrict__ out) {
    size_t n4 = (size_t)BB * NN * DD / 4;
    const float4* src = reinterpret_cast<const float4*>(x);
    float4*       dst = reinterpret_cast<float4*>(out);
    for (size_t i = blockIdx.x * (size_t)blockDim.x + threadIdx.x; i < n4;
         i += (size_t)gridDim.x * blockDim.x)
        dst[i] = src[i];
}

// ---------------------------------------------------------------------------
// 4) Gather selected rows + RNA round to tf32 -> g_a
// ---------------------------------------------------------------------------
__global__ void gather_rna_kernel(const float* __restrict__ x) {
    int m = blockIdx.x;
    int c = threadIdx.x;
    int tok = g_sel[m];
    size_t src = ((size_t)(m >> 11) * NN + tok) * DD + c * 4;
    float4 v = *reinterpret_cast<const float4*>(x + src);
    v.x = rna_tf32(v.x); v.y = rna_tf32(v.y); v.z = rna_tf32(v.z); v.w = rna_tf32(v.w);
    *reinterpret_cast<float4*>(g_a + (size_t)m * DD + c * 4) = v;
}

// ---------------------------------------------------------------------------
// 5) Transpose + RNA round: dst[c*R + r] = rna(src[r*C + c])
// ---------------------------------------------------------------------------
template <int R, int C, int WHICH>
__global__ void transpose_rna_kernel(const float* __restrict__ src) {
    __shared__ float t[32][33];
    float* dst = WHICH == 0 ? g_w1t : g_w2t;
    int bx = blockIdx.x * 32, by = blockIdx.y * 32;
    int tx = threadIdx.x, ty = threadIdx.y;
#pragma unroll
    for (int i = 0; i < 32; i += 8)
        t[ty + i][tx] = src[(size_t)(by + ty + i) * C + bx + tx];
    __syncthreads();
#pragma unroll
    for (int i = 0; i < 32; i += 8)
        dst[(size_t)(bx + ty + i) * R + by + tx] = rna_tf32(t[tx][ty + i]);
}

// ---------------------------------------------------------------------------
// tf32 mma.sync GEMM:  C[128x128 tile] = A[M,K] @ B[N,K]^T
//   MODE 0: ffn1  A=g_a (K=1024), B=g_w1t  ->  g_h = rna(gelu(C + b1))
//   MODE 1: ffn2  A=g_h (K=4096), B=g_w2t  ->  out[sel] = x[sel] + C + b2
// 256 threads, 8 warps 4(M) x 2(N), warp tile 32x64 = 2x8 m16n8k8 tiles.
// cp.async double buffer; smem rows padded to 36 floats (conflict-free frags).
// ---------------------------------------------------------------------------
#define SPITCH 36
#define STG_FLOATS (128 * SPITCH)                 // 4608 floats / 18KB per operand-stage
#define GSMEM_SZ (4 * STG_FLOATS * 4)             // A0 A1 B0 B1 = 73728 B

template <int MODE>
__device__ __forceinline__ void ld_stage(uint32_t sb, int stage,
                                         const float* __restrict__ A,
                                         const float* __restrict__ Bw,
                                         int Kdim, int mt, int nt, int k0, int tid) {
    uint32_t abase = sb + stage * (STG_FLOATS * 4);
    uint32_t bbase = sb + (2 + stage) * (STG_FLOATS * 4);
#pragma unroll
    for (int i = 0; i < 4; ++i) {
        int lin = i * 256 + tid;
        int row = lin >> 3, ch = lin & 7;
        CP_ASYNC16(abase + row * (SPITCH * 4) + ch * 16,
                   A + (size_t)(mt * 128 + row) * Kdim + k0 + ch * 4);
    }
#pragma unroll
    for (int i = 0; i < 4; ++i) {
        int lin = i * 256 + tid;
        int row = lin >> 3, ch = lin & 7;
        CP_ASYNC16(bbase + row * (SPITCH * 4) + ch * 16,
                   Bw + (size_t)(nt * 128 + row) * Kdim + k0 + ch * 4);
    }
}

template <int MODE>
__global__ __launch_bounds__(256)
void mma_gemm(const float* __restrict__ bias,
              const float* __restrict__ xin,
              float* __restrict__ outp) {
    extern __shared__ float smf[];
    const float* A    = (MODE == 0) ? g_a   : g_h;
    const float* Bw   = (MODE == 0) ? g_w1t : g_w2t;
    const int    Kdim = (MODE == 0) ? DD : DFFN;
    const int    KT   = Kdim / 32;

    int tid = threadIdx.x, lane = tid & 31, wid = tid >> 5;
    int wm = wid >> 1, wn = wid & 1;            // warp tile: rows wm*32, cols wn*64
    int mt = blockIdx.y, nt = blockIdx.x;
    uint32_t sb = smem_u32(smf);

    int r = lane >> 2, c = lane & 3;

    float acc[2][8][4];
#pragma unroll
    for (int mi = 0; mi < 2; ++mi)
#pragma unroll
        for (int ni = 0; ni < 8; ++ni)
#pragma unroll
            for (int q = 0; q < 4; ++q) acc[mi][ni][q] = 0.0f;

    ld_stage<MODE>(sb, 0, A, Bw, Kdim, mt, nt, 0, tid);
    CP_COMMIT();

    for (int k = 0; k < KT; ++k) {
        if (k + 1 < KT) {
            ld_stage<MODE>(sb, (k + 1) & 1, A, Bw, Kdim, mt, nt, (k + 1) * 32, tid);
            CP_COMMIT();
            CP_WAIT1();
        } else {
            CP_WAIT0();
        }
        __syncthreads();

        const float* As = smf + (k & 1) * STG_FLOATS;
        const float* Bs = smf + (2 + (k & 1)) * STG_FLOATS;
#pragma unroll
        for (int ks = 0; ks < 4; ++ks) {
            uint32_t a[2][4];
#pragma unroll
            for (int mi = 0; mi < 2; ++mi) {
                const float* ap = As + (wm * 32 + mi * 16 + r) * SPITCH + ks * 8 + c;
                a[mi][0] = __float_as_uint(ap[0]);
                a[mi][1] = __float_as_uint(ap[8 * SPITCH]);
                a[mi][2] = __float_as_uint(ap[4]);
                a[mi][3] = __float_as_uint(ap[8 * SPITCH + 4]);
            }
#pragma unroll
            for (int ni = 0; ni < 8; ++ni) {
                const float* bp = Bs + (wn * 64 + ni * 8 + r) * SPITCH + ks * 8 + c;
                uint32_t b0 = __float_as_uint(bp[0]);
                uint32_t b1 = __float_as_uint(bp[4]);
                MMA_TF32(acc[0][ni], a[0], b0, b1);
                MMA_TF32(acc[1][ni], a[1], b0, b1);
            }
        }
        __syncthreads();
    }

    // ---------------- Epilogue ----------------
    // c0/c1: row = r,  cols 2c, 2c+1 ; c2/c3: row = r+8
    if (MODE == 0) {
#pragma unroll
        for (int mi = 0; mi < 2; ++mi) {
#pragma unroll
            for (int half = 0; half < 2; ++half) {
                int m = mt * 128 + wm * 32 + mi * 16 + half * 8 + r;
                float* hrow = g_h + (size_t)m * DFFN;
#pragma unroll
                for (int ni = 0; ni < 8; ++ni) {
                    int n = nt * 128 + wn * 64 + ni * 8 + c * 2;
                    float v0 = acc[mi][ni][half * 2 + 0] + bias[n];
                    float v1 = acc[mi][ni][half * 2 + 1] + bias[n + 1];
                    float2 w;
                    w.x = rna_tf32(gelu_tanh(v0));
                    w.y = rna_tf32(gelu_tanh(v1));
                    *reinterpret_cast<float2*>(hrow + n) = w;
                }
            }
        }
    } else {
#pragma unroll
        for (int mi = 0; mi < 2; ++mi) {
#pragma unroll
            for (int half = 0; half < 2; ++half) {
                int m = mt * 128 + wm * 32 + mi * 16 + half * 8 + r;
                int tok = g_sel[m];
                size_t base = ((size_t)(m >> 11) * NN + tok) * DD;
#pragma unroll
                for (int ni = 0; ni < 8; ++ni) {
                    int n = nt * 128 + wn * 64 + ni * 8 + c * 2;
                    float2 xv = *reinterpret_cast<const float2*>(xin + base + n);
                    float2 w;
                    w.x = xv.x + acc[mi][ni][half * 2 + 0] + bias[n];
                    w.y = xv.y + acc[mi][ni][half * 2 + 1] + bias[n + 1];
                    *reinterpret_cast<float2*>(outp + base + n) = w;
                }
            }
        }
    }
}

// ---------------------------------------------------------------------------
// Launch: x, gate_w, w1, b1, w2, b2, k
// ---------------------------------------------------------------------------
extern "C" void kernel_launch(void* const* d_in, const int* in_sizes, int n_in,
                              void* d_out, int out_size) {
    const float* x  = (const float*)d_in[0];
    const float* gw = (const float*)d_in[1];
    const float* w1 = (const float*)d_in[2];
    const float* b1 = (const float*)d_in[3];
    const float* w2 = (const float*)d_in[4];
    const float* b2 = (const float*)d_in[5];
    float* out = (float*)d_out;

    cudaFuncSetAttribute(mma_gemm<0>, cudaFuncAttributeMaxDynamicSharedMemorySize, GSMEM_SZ);
    cudaFuncSetAttribute(mma_gemm<1>, cudaFuncAttributeMaxDynamicSharedMemorySize, GSMEM_SZ);

    scores_kernel<<<(BB * NN) / 8, 256>>>(x, gw);
    topk_kernel<<<BB, 1024>>>();
    copy_kernel<<<4096, 256>>>(x, out);
    gather_rna_kernel<<<MM, 256>>>(x);
    transpose_rna_kernel<DD, DFFN, 0><<<dim3(DFFN / 32, DD / 32), dim3(32, 8)>>>(w1);
    transpose_rna_kernel<DFFN, DD, 1><<<dim3(DD / 32, DFFN / 32), dim3(32, 8)>>>(w2);

    // GEMM1: g_a[8192,1024] @ w1 -> g_h[8192,4096]  (gelu fused)
    mma_gemm<0><<<dim3(DFFN / 128, MM / 128), 256, GSMEM_SZ>>>(b1, nullptr, nullptr);
    // GEMM2: g_h @ w2 + residual -> scattered into out
    mma_gemm<1><<<dim3(DD / 128, MM / 128), 256, GSMEM_SZ>>>(b2, x, out);
}

// round 6
// speedup vs baseline: 3.4387x; 1.0174x over previous
#include <cuda_runtime.h>
#include <cstdint>
#include <math.h>

// Problem constants (MoDRouter_48387101556956: fixed shapes)
#define BB   4
#define NN   4096
#define DD   1024
#define DFFN 4096
#define KK   2048
#define MM   (BB * KK)   // 8192 selected tokens total

// ---------------------------------------------------------------------------
// Device scratch
// ---------------------------------------------------------------------------
__device__ float g_scores[BB * NN];
__device__ int   g_sel[MM];                       // selected token idx per (b,j)
__device__ float g_a[(size_t)MM * DD];            // gathered + tf32-rounded A (32 MB)
__device__ float g_w1t[(size_t)DFFN * DD];        // w1^T (n-major, K contig), tf32-rounded
__device__ float g_w2t[(size_t)DD * DFFN];        // w2^T (n-major, K contig), tf32-rounded
__device__ float g_h[(size_t)MM * DFFN];          // gelu(x@w1+b1), tf32-rounded (128 MB)

// ---------------------------------------------------------------------------
// Helpers
// ---------------------------------------------------------------------------
__device__ __forceinline__ uint32_t smem_u32(const void* p) {
    uint32_t a;
    asm("{ .reg .u64 t; cvta.to.shared.u64 t, %1; cvt.u32.u64 %0, t; }" : "=r"(a) : "l"(p));
    return a;
}
__device__ __forceinline__ float rna_tf32(float f) {
    uint32_t u;
    asm("cvt.rna.tf32.f32 %0, %1;" : "=r"(u) : "f"(f));
    return __uint_as_float(u);
}
__device__ __forceinline__ float gelu_tanh(float u) {
    float t = tanhf(0.7978845608028654f * (u + 0.044715f * u * u * u));
    return 0.5f * u * (1.0f + t);
}

#define CP_ASYNC16(dst, src) \
    asm volatile("cp.async.cg.shared.global [%0], [%1], 16;" :: "r"(dst), "l"(src) : "memory")
#define CP_COMMIT() asm volatile("cp.async.commit_group;" ::: "memory")
#define CP_WAIT1()  asm volatile("cp.async.wait_group 1;" ::: "memory")

// m16n8k8 row.col tf32 MMA, fp32 accumulate (base-ISA, legal on sm_103)
#define MMA_TF32(c, a, b0, b1)                                                        \
    asm volatile("mma.sync.aligned.m16n8k8.row.col.f32.tf32.tf32.f32 "                \
                 "{%0,%1,%2,%3}, {%4,%5,%6,%7}, {%8,%9}, {%0,%1,%2,%3};"              \
                 : "+f"((c)[0]), "+f"((c)[1]), "+f"((c)[2]), "+f"((c)[3])             \
                 : "r"((a)[0]), "r"((a)[1]), "r"((a)[2]), "r"((a)[3]), "r"(b0), "r"(b1))

// ---------------------------------------------------------------------------
// 1) Gate scores + out=x copy fused — one warp per row (reads the row anyway)
// ---------------------------------------------------------------------------
__global__ void scores_copy_kernel(const float* __restrict__ x,
                                   const float* __restrict__ gw,
                                   float* __restrict__ out) {
    int gwarp = (blockIdx.x * blockDim.x + threadIdx.x) >> 5;
    int lane  = threadIdx.x & 31;
    if (gwarp >= BB * NN) return;
    const float4* xr = reinterpret_cast<const float4*>(x + (size_t)gwarp * DD);
    float4*       orow = reinterpret_cast<float4*>(out + (size_t)gwarp * DD);
    const float4* g4 = reinterpret_cast<const float4*>(gw);
    float s = 0.0f;
#pragma unroll
    for (int i = 0; i < DD / 4 / 32; ++i) {
        float4 a = xr[lane + i * 32];
        float4 b = g4[lane + i * 32];
        orow[lane + i * 32] = a;                      // fused copy
        s += a.x * b.x + a.y * b.y + a.z * b.z + a.w * b.w;
    }
#pragma unroll
    for (int o = 16; o; o >>= 1) s += __shfl_xor_sync(0xFFFFFFFFu, s, o);
    if (lane == 0) g_scores[gwarp] = s;
}

// ---------------------------------------------------------------------------
// 2) Per-batch top-K via bitonic sort
// ---------------------------------------------------------------------------
__global__ void topk_kernel() {
    __shared__ float key[NN];
    __shared__ int   val[NN];
    int b = blockIdx.x;
    for (int i = threadIdx.x; i < NN; i += blockDim.x) { key[i] = g_scores[b * NN + i]; val[i] = i; }
    __syncthreads();
    for (int k = 2; k <= NN; k <<= 1)
        for (int j = k >> 1; j > 0; j >>= 1) {
            for (int i = threadIdx.x; i < NN; i += blockDim.x) {
                int ixj = i ^ j;
                if (ixj > i) {
                    bool up = ((i & k) == 0);
                    float ki = key[i], kj = key[ixj];
                    if (up ? (ki > kj) : (ki < kj)) {
                        key[i] = kj; key[ixj] = ki;
                        int t = val[i]; val[i] = val[ixj]; val[ixj] = t;
                    }
                }
            }
            __syncthreads();
        }
    for (int i = threadIdx.x; i < KK; i += blockDim.x)
        g_sel[b * KK + i] = val[NN - 1 - i];
}

// ---------------------------------------------------------------------------
// 3) Gather selected rows + RNA round to tf32 -> g_a
// ---------------------------------------------------------------------------
__global__ void gather_rna_kernel(const float* __restrict__ x) {
    int m = blockIdx.x;
    int c = threadIdx.x;
    int tok = g_sel[m];
    size_t src = ((size_t)(m >> 11) * NN + tok) * DD + c * 4;
    float4 v = *reinterpret_cast<const float4*>(x + src);
    v.x = rna_tf32(v.x); v.y = rna_tf32(v.y); v.z = rna_tf32(v.z); v.w = rna_tf32(v.w);
    *reinterpret_cast<float4*>(g_a + (size_t)m * DD + c * 4) = v;
}

// ---------------------------------------------------------------------------
// 4) Transpose + RNA round: dst[c*R + r] = rna(src[r*C + c])
// ---------------------------------------------------------------------------
template <int R, int C, int WHICH>
__global__ void transpose_rna_kernel(const float* __restrict__ src) {
    __shared__ float t[32][33];
    float* dst = WHICH == 0 ? g_w1t : g_w2t;
    int bx = blockIdx.x * 32, by = blockIdx.y * 32;
    int tx = threadIdx.x, ty = threadIdx.y;
#pragma unroll
    for (int i = 0; i < 32; i += 8)
        t[ty + i][tx] = src[(size_t)(by + ty + i) * C + bx + tx];
    __syncthreads();
#pragma unroll
    for (int i = 0; i < 32; i += 8)
        dst[(size_t)(bx + ty + i) * R + by + tx] = rna_tf32(t[tx][ty + i]);
}

// ---------------------------------------------------------------------------
// tf32 mma.sync GEMM:  C[128x128 tile] = A[M,K] @ B[N,K]^T
//   MODE 0: ffn1  A=g_a (K=1024), B=g_w1t  ->  g_h = rna(gelu(C + b1))
//   MODE 1: ffn2  A=g_h (K=4096), B=g_w2t  ->  out[sel] = x[sel] + C + b2
// 256 threads, 8 warps 4(M) x 2(N), warp tile 32x64 = 2x8 m16n8k8 tiles.
// 3-stage cp.async pipeline, ONE __syncthreads per K-iter.
// smem rows padded to 36 floats (fragment loads conflict-free: bank = 4r+c).
// ---------------------------------------------------------------------------
#define SPITCH 36
#define STG_FLOATS (128 * SPITCH)                 // 4608 floats / 18KB per operand-stage
#define NSTG 3
#define GSMEM_SZ (2 * NSTG * STG_FLOATS * 4)      // A0..A2 B0..B2 = 110592 B

template <int MODE>
__device__ __forceinline__ void ld_stage(uint32_t sb, int stage,
                                         const float* __restrict__ A,
                                         const float* __restrict__ Bw,
                                         int Kdim, int mt, int nt, int k0, int tid) {
    uint32_t abase = sb + stage * (STG_FLOATS * 4);
    uint32_t bbase = sb + (NSTG + stage) * (STG_FLOATS * 4);
    int row = tid >> 3, ch = tid & 7;
    const float* ag = A  + (size_t)(mt * 128 + row) * Kdim + k0 + ch * 4;
    const float* bg = Bw + (size_t)(nt * 128 + row) * Kdim + k0 + ch * 4;
    uint32_t off = row * (SPITCH * 4) + ch * 16;
#pragma unroll
    for (int i = 0; i < 4; ++i) {
        CP_ASYNC16(abase + off + i * 32 * (SPITCH * 4), ag + (size_t)(i * 32) * Kdim);
        CP_ASYNC16(bbase + off + i * 32 * (SPITCH * 4), bg + (size_t)(i * 32) * Kdim);
    }
}

template <int MODE>
__global__ __launch_bounds__(256, 2)
void mma_gemm(const float* __restrict__ bias,
              const float* __restrict__ xin,
              float* __restrict__ outp) {
    extern __shared__ float smf[];
    const float* A    = (MODE == 0) ? g_a   : g_h;
    const float* Bw   = (MODE == 0) ? g_w1t : g_w2t;
    const int    Kdim = (MODE == 0) ? DD : DFFN;
    const int    KT   = Kdim / 32;

    int tid = threadIdx.x, lane = tid & 31, wid = tid >> 5;
    int wm = wid >> 1, wn = wid & 1;            // warp tile: rows wm*32, cols wn*64
    int mt = blockIdx.y, nt = blockIdx.x;
    uint32_t sb = smem_u32(smf);

    int r = lane >> 2, c = lane & 3;

    float acc[2][8][4];
#pragma unroll
    for (int mi = 0; mi < 2; ++mi)
#pragma unroll
        for (int ni = 0; ni < 8; ++ni)
#pragma unroll
            for (int q = 0; q < 4; ++q) acc[mi][ni][q] = 0.0f;

    // prologue: 2 stages in flight
    ld_stage<MODE>(sb, 0, A, Bw, Kdim, mt, nt, 0, tid);
    CP_COMMIT();
    ld_stage<MODE>(sb, 1, A, Bw, Kdim, mt, nt, 32, tid);
    CP_COMMIT();

    int stage = 0;           // stage holding iteration k
    for (int k = 0; k < KT; ++k) {
        CP_WAIT1();          // group k complete (k+1 may stay pending)
        __syncthreads();     // all warps see stage data; all done with stage (k+2)%3

        // prefetch k+2 into the buffer vacated at iter k-1
        int pstage = stage + 2 >= NSTG ? stage + 2 - NSTG : stage + 2;
        if (k + 2 < KT)
            ld_stage<MODE>(sb, pstage, A, Bw, Kdim, mt, nt, (k + 2) * 32, tid);
        CP_COMMIT();         // empty group near the tail keeps wait counts aligned

        const float* As = smf + stage * STG_FLOATS;
        const float* Bs = smf + (NSTG + stage) * STG_FLOATS;
#pragma unroll
        for (int ks = 0; ks < 4; ++ks) {
            uint32_t a[2][4];
#pragma unroll
            for (int mi = 0; mi < 2; ++mi) {
                const float* ap = As + (wm * 32 + mi * 16 + r) * SPITCH + ks * 8 + c;
                a[mi][0] = __float_as_uint(ap[0]);
                a[mi][1] = __float_as_uint(ap[8 * SPITCH]);
                a[mi][2] = __float_as_uint(ap[4]);
                a[mi][3] = __float_as_uint(ap[8 * SPITCH + 4]);
            }
#pragma unroll
            for (int ni = 0; ni < 8; ++ni) {
                const float* bp = Bs + (wn * 64 + ni * 8 + r) * SPITCH + ks * 8 + c;
                uint32_t b0 = __float_as_uint(bp[0]);
                uint32_t b1 = __float_as_uint(bp[4]);
                MMA_TF32(acc[0][ni], a[0], b0, b1);
                MMA_TF32(acc[1][ni], a[1], b0, b1);
            }
        }
        stage = stage + 1 == NSTG ? 0 : stage + 1;
    }

    // ---------------- Epilogue ----------------
    // c0/c1: row = r, cols 2c,2c+1 ; c2/c3: row = r+8
    if (MODE == 0) {
#pragma unroll
        for (int mi = 0; mi < 2; ++mi) {
#pragma unroll
            for (int half = 0; half < 2; ++half) {
                int m = mt * 128 + wm * 32 + mi * 16 + half * 8 + r;
                float* hrow = g_h + (size_t)m * DFFN;
#pragma unroll
                for (int ni = 0; ni < 8; ++ni) {
                    int n = nt * 128 + wn * 64 + ni * 8 + c * 2;
                    float v0 = acc[mi][ni][half * 2 + 0] + bias[n];
                    float v1 = acc[mi][ni][half * 2 + 1] + bias[n + 1];
                    float2 w;
                    w.x = rna_tf32(gelu_tanh(v0));
                    w.y = rna_tf32(gelu_tanh(v1));
                    *reinterpret_cast<float2*>(hrow + n) = w;
                }
            }
        }
    } else {
#pragma unroll
        for (int mi = 0; mi < 2; ++mi) {
#pragma unroll
            for (int half = 0; half < 2; ++half) {
                int m = mt * 128 + wm * 32 + mi * 16 + half * 8 + r;
                int tok = g_sel[m];
                size_t base = ((size_t)(m >> 11) * NN + tok) * DD;
#pragma unroll
                for (int ni = 0; ni < 8; ++ni) {
                    int n = nt * 128 + wn * 64 + ni * 8 + c * 2;
                    float2 xv = *reinterpret_cast<const float2*>(xin + base + n);
                    float2 w;
                    w.x = xv.x + acc[mi][ni][half * 2 + 0] + bias[n];
                    w.y = xv.y + acc[mi][ni][half * 2 + 1] + bias[n + 1];
                    *reinterpret_cast<float2*>(outp + base + n) = w;
                }
            }
        }
    }
}

// ---------------------------------------------------------------------------
// Launch: x, gate_w, w1, b1, w2, b2, k
// Order chosen so mma_gemm<0> is the 6th launch (ncu -s 5 -c 1 target).
// ---------------------------------------------------------------------------
extern "C" void kernel_launch(void* const* d_in, const int* in_sizes, int n_in,
                              void* d_out, int out_size) {
    const float* x  = (const float*)d_in[0];
    const float* gw = (const float*)d_in[1];
    const float* w1 = (const float*)d_in[2];
    const float* b1 = (const float*)d_in[3];
    const float* w2 = (const float*)d_in[4];
    const float* b2 = (const float*)d_in[5];
    float* out = (float*)d_out;

    cudaFuncSetAttribute(mma_gemm<0>, cudaFuncAttributeMaxDynamicSharedMemorySize, GSMEM_SZ);
    cudaFuncSetAttribute(mma_gemm<1>, cudaFuncAttributeMaxDynamicSharedMemorySize, GSMEM_SZ);

    scores_copy_kernel<<<(BB * NN) / 8, 256>>>(x, gw, out);                              // 1
    topk_kernel<<<BB, 1024>>>();                                                         // 2
    gather_rna_kernel<<<MM, 256>>>(x);                                                   // 3
    transpose_rna_kernel<DD, DFFN, 0><<<dim3(DFFN / 32, DD / 32), dim3(32, 8)>>>(w1);    // 4
    transpose_rna_kernel<DFFN, DD, 1><<<dim3(DD / 32, DFFN / 32), dim3(32, 8)>>>(w2);    // 5
    // GEMM1: g_a[8192,1024] @ w1 -> g_h[8192,4096]  (gelu fused)
    mma_gemm<0><<<dim3(DFFN / 128, MM / 128), 256, GSMEM_SZ>>>(b1, nullptr, nullptr);    // 6
    // GEMM2: g_h @ w2 + residual -> scattered into out
    mma_gemm<1><<<dim3(DD / 128, MM / 128), 256, GSMEM_SZ>>>(b2, x, out);                // 7
}

// round 7
// speedup vs baseline: 5.9944x; 1.7432x over previous
#include <cuda_runtime.h>
#include <cuda_fp16.h>
#include <cstdint>
#include <math.h>

// Problem constants (MoDRouter_48387101556956: fixed shapes)
#define BB   4
#define NN   4096
#define DD   1024
#define DFFN 4096
#define KK   2048
#define MM   (BB * KK)   // 8192 selected tokens total

// ---------------------------------------------------------------------------
// Device scratch
// ---------------------------------------------------------------------------
__device__ float  g_scores[BB * NN];
__device__ int    g_sel[MM];                       // selected token idx per (b,j)
__device__ __half g_a[(size_t)MM * DD];            // gathered + fp16 A (16 MB)
__device__ __half g_w1t[(size_t)DFFN * DD];        // w1^T (n-major, K contig), fp16
__device__ __half g_w2t[(size_t)DD * DFFN];        // w2^T (n-major, K contig), fp16
__device__ __half g_h[(size_t)MM * DFFN];          // gelu(x@w1+b1), fp16 (64 MB)

// ---------------------------------------------------------------------------
// Helpers
// ---------------------------------------------------------------------------
__device__ __forceinline__ uint32_t smem_u32(const void* p) {
    uint32_t a;
    asm("{ .reg .u64 t; cvta.to.shared.u64 t, %1; cvt.u32.u64 %0, t; }" : "=r"(a) : "l"(p));
    return a;
}
__device__ __forceinline__ float gelu_tanh(float u) {
    float t = tanhf(0.7978845608028654f * (u + 0.044715f * u * u * u));
    return 0.5f * u * (1.0f + t);
}

#define CP_ASYNC16(dst, src) \
    asm volatile("cp.async.cg.shared.global [%0], [%1], 16;" :: "r"(dst), "l"(src) : "memory")
#define CP_COMMIT() asm volatile("cp.async.commit_group;" ::: "memory")
#define CP_WAIT1()  asm volatile("cp.async.wait_group 1;" ::: "memory")

// m16n8k16 row.col fp16 MMA, fp32 accumulate (base-ISA, legal on sm_103)
#define MMA_F16(c, a, b0, b1)                                                         \
    asm volatile("mma.sync.aligned.m16n8k16.row.col.f32.f16.f16.f32 "                 \
                 "{%0,%1,%2,%3}, {%4,%5,%6,%7}, {%8,%9}, {%0,%1,%2,%3};"              \
                 : "+f"((c)[0]), "+f"((c)[1]), "+f"((c)[2]), "+f"((c)[3])             \
                 : "r"((a)[0]), "r"((a)[1]), "r"((a)[2]), "r"((a)[3]), "r"(b0), "r"(b1))

// ---------------------------------------------------------------------------
// 1) Gate scores + out=x copy fused — one warp per row (reads the row anyway)
// ---------------------------------------------------------------------------
__global__ void scores_copy_kernel(const float* __restrict__ x,
                                   const float* __restrict__ gw,
                                   float* __restrict__ out) {
    int gwarp = (blockIdx.x * blockDim.x + threadIdx.x) >> 5;
    int lane  = threadIdx.x & 31;
    if (gwarp >= BB * NN) return;
    const float4* xr = reinterpret_cast<const float4*>(x + (size_t)gwarp * DD);
    float4*       orow = reinterpret_cast<float4*>(out + (size_t)gwarp * DD);
    const float4* g4 = reinterpret_cast<const float4*>(gw);
    float s = 0.0f;
#pragma unroll
    for (int i = 0; i < DD / 4 / 32; ++i) {
        float4 a = xr[lane + i * 32];
        float4 b = g4[lane + i * 32];
        orow[lane + i * 32] = a;                      // fused copy
        s += a.x * b.x + a.y * b.y + a.z * b.z + a.w * b.w;
    }
#pragma unroll
    for (int o = 16; o; o >>= 1) s += __shfl_xor_sync(0xFFFFFFFFu, s, o);
    if (lane == 0) g_scores[gwarp] = s;
}

// ---------------------------------------------------------------------------
// 2) Per-batch top-K via bitonic sort
// ---------------------------------------------------------------------------
__global__ void topk_kernel() {
    __shared__ float key[NN];
    __shared__ int   val[NN];
    int b = blockIdx.x;
    for (int i = threadIdx.x; i < NN; i += blockDim.x) { key[i] = g_scores[b * NN + i]; val[i] = i; }
    __syncthreads();
    for (int k = 2; k <= NN; k <<= 1)
        for (int j = k >> 1; j > 0; j >>= 1) {
            for (int i = threadIdx.x; i < NN; i += blockDim.x) {
                int ixj = i ^ j;
                if (ixj > i) {
                    bool up = ((i & k) == 0);
                    float ki = key[i], kj = key[ixj];
                    if (up ? (ki > kj) : (ki < kj)) {
                        key[i] = kj; key[ixj] = ki;
                        int t = val[i]; val[i] = val[ixj]; val[ixj] = t;
                    }
                }
            }
            __syncthreads();
        }
    for (int i = threadIdx.x; i < KK; i += blockDim.x)
        g_sel[b * KK + i] = val[NN - 1 - i];
}

// ---------------------------------------------------------------------------
// 3) Gather selected rows + convert fp16 -> g_a
// ---------------------------------------------------------------------------
__global__ void gather_h_kernel(const float* __restrict__ x) {
    int m = blockIdx.x;
    int c = threadIdx.x;                 // 4 floats -> 4 halves each
    int tok = g_sel[m];
    size_t src = ((size_t)(m >> 11) * NN + tok) * DD + c * 4;
    float4 v = *reinterpret_cast<const float4*>(x + src);
    __half2 h0 = __floats2half2_rn(v.x, v.y);
    __half2 h1 = __floats2half2_rn(v.z, v.w);
    uint2 pk;
    pk.x = *reinterpret_cast<uint32_t*>(&h0);
    pk.y = *reinterpret_cast<uint32_t*>(&h1);
    *reinterpret_cast<uint2*>(g_a + (size_t)m * DD + c * 4) = pk;
}

// ---------------------------------------------------------------------------
// 4) Transpose + convert fp16: dst[c*R + r] = h(src[r*C + c])
// ---------------------------------------------------------------------------
template <int R, int C, int WHICH>
__global__ void transpose_h_kernel(const float* __restrict__ src) {
    __shared__ float t[32][33];
    __half* dst = WHICH == 0 ? g_w1t : g_w2t;
    int bx = blockIdx.x * 32, by = blockIdx.y * 32;
    int tx = threadIdx.x, ty = threadIdx.y;
#pragma unroll
    for (int i = 0; i < 32; i += 8)
        t[ty + i][tx] = src[(size_t)(by + ty + i) * C + bx + tx];
    __syncthreads();
#pragma unroll
    for (int i = 0; i < 32; i += 8)
        dst[(size_t)(bx + ty + i) * R + by + tx] = __float2half_rn(t[tx][ty + i]);
}

// ---------------------------------------------------------------------------
// fp16 mma.sync GEMM:  C[128x128 tile] = A[M,K] @ B[N,K]^T  (fp32 accumulate)
//   MODE 0: ffn1  A=g_a (K=1024), B=g_w1t  ->  g_h = h(gelu(C + b1))
//   MODE 1: ffn2  A=g_h (K=4096), B=g_w2t  ->  out[sel] = x[sel] + C + b2
// 256 threads, 8 warps 4(M) x 2(N), warp tile 32x64 = 2x8 m16n8k16 tiles.
// BK=64, 3-stage cp.async pipeline, ONE __syncthreads per K-iter.
// smem row pitch 72 halves (=36 words): fragment bank = (4r+c) mod 32, all distinct.
// ---------------------------------------------------------------------------
#define HPITCH_W 36                                // words per row (72 halves)
#define STG_BYTES (128 * HPITCH_W * 4)             // 18432 B per operand-stage
#define NSTG 3
#define GSMEM_SZ (2 * NSTG * STG_BYTES)            // 110592 B

__device__ __forceinline__ void ld_stage(uint32_t sb, int stage,
                                         const __half* __restrict__ A,
                                         const __half* __restrict__ Bw,
                                         int Kdim, int mt, int nt, int k0, int tid) {
    uint32_t abase = sb + stage * STG_BYTES;
    uint32_t bbase = sb + (NSTG + stage) * STG_BYTES;
    int row = tid >> 3, ch = tid & 7;              // 8 x 16B chunks cover 64 halves
    const __half* ag = A  + (size_t)(mt * 128 + row) * Kdim + k0 + ch * 8;
    const __half* bg = Bw + (size_t)(nt * 128 + row) * Kdim + k0 + ch * 8;
    uint32_t off = row * (HPITCH_W * 4) + ch * 16;
#pragma unroll
    for (int i = 0; i < 4; ++i) {
        CP_ASYNC16(abase + off + i * 32 * (HPITCH_W * 4), ag + (size_t)(i * 32) * Kdim);
        CP_ASYNC16(bbase + off + i * 32 * (HPITCH_W * 4), bg + (size_t)(i * 32) * Kdim);
    }
}

template <int MODE>
__global__ __launch_bounds__(256, 2)
void mma_gemm(const float* __restrict__ bias,
              const float* __restrict__ xin,
              float* __restrict__ outp) {
    extern __shared__ uint32_t smw[];
    const __half* A    = (MODE == 0) ? g_a   : g_h;
    const __half* Bw   = (MODE == 0) ? g_w1t : g_w2t;
    const int     Kdim = (MODE == 0) ? DD : DFFN;
    const int     KT   = Kdim / 64;

    int tid = threadIdx.x, lane = tid & 31, wid = tid >> 5;
    int wm = wid >> 1, wn = wid & 1;               // warp tile: rows wm*32, cols wn*64
    int mt = blockIdx.y, nt = blockIdx.x;
    uint32_t sb = smem_u32(smw);

    int r = lane >> 2, c = lane & 3;

    float acc[2][8][4];
#pragma unroll
    for (int mi = 0; mi < 2; ++mi)
#pragma unroll
        for (int ni = 0; ni < 8; ++ni)
#pragma unroll
            for (int q = 0; q < 4; ++q) acc[mi][ni][q] = 0.0f;

    // prologue: 2 stages in flight
    ld_stage(sb, 0, A, Bw, Kdim, mt, nt, 0, tid);
    CP_COMMIT();
    ld_stage(sb, 1, A, Bw, Kdim, mt, nt, 64, tid);
    CP_COMMIT();

    int stage = 0;
    for (int k = 0; k < KT; ++k) {
        CP_WAIT1();
        __syncthreads();

        int pstage = stage + 2 >= NSTG ? stage + 2 - NSTG : stage + 2;
        if (k + 2 < KT)
            ld_stage(sb, pstage, A, Bw, Kdim, mt, nt, (k + 2) * 64, tid);
        CP_COMMIT();

        const uint32_t* As = smw + stage * (STG_BYTES / 4);
        const uint32_t* Bs = smw + (NSTG + stage) * (STG_BYTES / 4);
#pragma unroll
        for (int ks = 0; ks < 4; ++ks) {           // 4 x K=16
            uint32_t a[2][4];
#pragma unroll
            for (int mi = 0; mi < 2; ++mi) {
                const uint32_t* ap = As + (wm * 32 + mi * 16 + r) * HPITCH_W + ks * 8 + c;
                a[mi][0] = ap[0];
                a[mi][1] = ap[8 * HPITCH_W];
                a[mi][2] = ap[4];
                a[mi][3] = ap[8 * HPITCH_W + 4];
            }
#pragma unroll
            for (int ni = 0; ni < 8; ++ni) {
                const uint32_t* bp = Bs + (wn * 64 + ni * 8 + r) * HPITCH_W + ks * 8 + c;
                uint32_t b0 = bp[0];
                uint32_t b1 = bp[4];
                MMA_F16(acc[0][ni], a[0], b0, b1);
                MMA_F16(acc[1][ni], a[1], b0, b1);
            }
        }
        stage = stage + 1 == NSTG ? 0 : stage + 1;
    }

    // ---------------- Epilogue ----------------
    // c0/c1: row = r, cols 2c,2c+1 ; c2/c3: row = r+8
    if (MODE == 0) {
#pragma unroll
        for (int mi = 0; mi < 2; ++mi) {
#pragma unroll
            for (int half = 0; half < 2; ++half) {
                int m = mt * 128 + wm * 32 + mi * 16 + half * 8 + r;
                __half* hrow = g_h + (size_t)m * DFFN;
#pragma unroll
                for (int ni = 0; ni < 8; ++ni) {
                    int n = nt * 128 + wn * 64 + ni * 8 + c * 2;
                    float v0 = gelu_tanh(acc[mi][ni][half * 2 + 0] + bias[n]);
                    float v1 = gelu_tanh(acc[mi][ni][half * 2 + 1] + bias[n + 1]);
                    __half2 hv = __floats2half2_rn(v0, v1);
                    *reinterpret_cast<__half2*>(hrow + n) = hv;
                }
            }
        }
    } else {
#pragma unroll
        for (int mi = 0; mi < 2; ++mi) {
#pragma unroll
            for (int half = 0; half < 2; ++half) {
                int m = mt * 128 + wm * 32 + mi * 16 + half * 8 + r;
                int tok = g_sel[m];
                size_t base = ((size_t)(m >> 11) * NN + tok) * DD;
#pragma unroll
                for (int ni = 0; ni < 8; ++ni) {
                    int n = nt * 128 + wn * 64 + ni * 8 + c * 2;
                    float2 xv = *reinterpret_cast<const float2*>(xin + base + n);
                    float2 w;
                    w.x = xv.x + acc[mi][ni][half * 2 + 0] + bias[n];
                    w.y = xv.y + acc[mi][ni][half * 2 + 1] + bias[n + 1];
                    *reinterpret_cast<float2*>(outp + base + n) = w;
                }
            }
        }
    }
}

// ---------------------------------------------------------------------------
// Launch: x, gate_w, w1, b1, w2, b2, k
// ---------------------------------------------------------------------------
extern "C" void kernel_launch(void* const* d_in, const int* in_sizes, int n_in,
                              void* d_out, int out_size) {
    const float* x  = (const float*)d_in[0];
    const float* gw = (const float*)d_in[1];
    const float* w1 = (const float*)d_in[2];
    const float* b1 = (const float*)d_in[3];
    const float* w2 = (const float*)d_in[4];
    const float* b2 = (const float*)d_in[5];
    float* out = (float*)d_out;

    cudaFuncSetAttribute(mma_gemm<0>, cudaFuncAttributeMaxDynamicSharedMemorySize, GSMEM_SZ);
    cudaFuncSetAttribute(mma_gemm<1>, cudaFuncAttributeMaxDynamicSharedMemorySize, GSMEM_SZ);

    scores_copy_kernel<<<(BB * NN) / 8, 256>>>(x, gw, out);                            // 1
    topk_kernel<<<BB, 1024>>>();                                                       // 2
    gather_h_kernel<<<MM, 256>>>(x);                                                   // 3
    transpose_h_kernel<DD, DFFN, 0><<<dim3(DFFN / 32, DD / 32), dim3(32, 8)>>>(w1);    // 4
    transpose_h_kernel<DFFN, DD, 1><<<dim3(DD / 32, DFFN / 32), dim3(32, 8)>>>(w2);    // 5
    // GEMM1: g_a[8192,1024] @ w1 -> g_h[8192,4096]  (gelu fused, fp16 out)
    mma_gemm<0><<<dim3(DFFN / 128, MM / 128), 256, GSMEM_SZ>>>(b1, nullptr, nullptr);  // 6
    // GEMM2: g_h @ w2 + residual -> scattered into out
    mma_gemm<1><<<dim3(DD / 128, MM / 128), 256, GSMEM_SZ>>>(b2, x, out);              // 7
}